// round 1
// baseline (speedup 1.0000x reference)
#include <cuda_runtime.h>
#include <math.h>

// Problem constants (fixed by the reference)
namespace {

constexpr int B_ = 8;
constexpr int T_ = 256;
constexpr int D_ = 12;    // embed dim == n_qubits
constexpr int H_ = 4;     // heads, hd = 3
constexpr int QPB = 128;  // queries per block
constexpr int BPB = T_ / QPB;  // blocks per batch = 2

// Shared-weight layout offsets (floats)
//  Wi 0..431 | bi 432..467 | Wo 468..611 | bo 612..623 | thA 624..635
//  W1 636..779 | b1 780..791 | thF 792..803 | W2 804..947 | b2 948..959
//  g1 960 | be1 972 | g2 984 | be2 996   (total 1008)

__global__ __launch_bounds__(QPB, 1) void qtb_kernel(
    const float* __restrict__ x,
    const float* __restrict__ Wi, const float* __restrict__ bi,
    const float* __restrict__ Wo, const float* __restrict__ bo,
    const float* __restrict__ thA,
    const float* __restrict__ W1, const float* __restrict__ b1,
    const float* __restrict__ thF,
    const float* __restrict__ W2, const float* __restrict__ b2,
    const float* __restrict__ g1, const float* __restrict__ be1,
    const float* __restrict__ g2, const float* __restrict__ be2,
    const int* __restrict__ mask,
    float* __restrict__ out)
{
    __shared__ float sK[T_][D_];   // row stride 48B -> float4-aligned
    __shared__ float sV[T_][D_];
    __shared__ float sW[1008];
    __shared__ int   sM[T_];

    const int b   = blockIdx.x / BPB;
    const int qc  = blockIdx.x % BPB;
    const int tid = threadIdx.x;

    // ---- cooperative weight staging -------------------------------------
    for (int i = tid; i < 432; i += QPB) sW[i] = Wi[i];
    for (int i = tid; i < 144; i += QPB) {
        sW[468 + i] = Wo[i];
        sW[636 + i] = W1[i];
        sW[804 + i] = W2[i];
    }
    if (tid < 36) sW[432 + tid] = bi[tid];
    if (tid < 12) {
        sW[612 + tid] = bo[tid];
        sW[624 + tid] = thA[tid];
        sW[780 + tid] = b1[tid];
        sW[792 + tid] = thF[tid];
        sW[948 + tid] = b2[tid];
        sW[960 + tid] = g1[tid];
        sW[972 + tid] = be1[tid];
        sW[984 + tid] = g2[tid];
        sW[996 + tid] = be2[tid];
    }
    __syncthreads();

    // ---- K / V for the whole batch (each thread does T_/QPB tokens) -----
    for (int tok = tid; tok < T_; tok += QPB) {
        const float* xg = x + (size_t)(b * T_ + tok) * D_;
        float xr[D_];
        #pragma unroll
        for (int i = 0; i < D_; i++) xr[i] = xg[i];
        #pragma unroll
        for (int r = 0; r < D_; r++) {
            float ak = sW[432 + 12 + r];
            float av = sW[432 + 24 + r];
            #pragma unroll
            for (int c = 0; c < D_; c++) {
                ak = fmaf(sW[(12 + r) * D_ + c], xr[c], ak);
                av = fmaf(sW[(24 + r) * D_ + c], xr[c], av);
            }
            sK[tok][r] = ak;
            sV[tok][r] = av;
        }
        sM[tok] = mask[b * T_ + tok];
    }

    // ---- this thread's query --------------------------------------------
    const int tq = qc * QPB + tid;
    float xr[D_];
    {
        const float* xg = x + (size_t)(b * T_ + tq) * D_;
        #pragma unroll
        for (int i = 0; i < D_; i++) xr[i] = xg[i];
    }
    float q[D_];
    #pragma unroll
    for (int r = 0; r < D_; r++) {
        float a = sW[432 + r];
        #pragma unroll
        for (int c = 0; c < D_; c++) a = fmaf(sW[r * D_ + c], xr[c], a);
        q[r] = a;
    }
    __syncthreads();

    // ---- attention: one-pass max-free softmax, 4 heads, hd=3 ------------
    const float scale = 0.57735026918962576451f;  // 1/sqrt(3)
    float l[H_];
    float acc[D_];
    #pragma unroll
    for (int h = 0; h < H_; h++) l[h] = 0.f;
    #pragma unroll
    for (int i = 0; i < D_; i++) acc[i] = 0.f;

    #pragma unroll 4
    for (int kk = 0; kk < T_; kk++) {
        float kr[D_], vr[D_];
        *(float4*)&kr[0] = *(const float4*)&sK[kk][0];
        *(float4*)&kr[4] = *(const float4*)&sK[kk][4];
        *(float4*)&kr[8] = *(const float4*)&sK[kk][8];
        *(float4*)&vr[0] = *(const float4*)&sV[kk][0];
        *(float4*)&vr[4] = *(const float4*)&sV[kk][4];
        *(float4*)&vr[8] = *(const float4*)&sV[kk][8];
        const bool msk = (sM[kk] != 0);
        #pragma unroll
        for (int h = 0; h < H_; h++) {
            float s = (q[3*h]   * kr[3*h]
                     + q[3*h+1] * kr[3*h+1]
                     + q[3*h+2] * kr[3*h+2]) * scale;
            s = msk ? -1e30f : s;
            const float p = __expf(s);
            l[h] += p;
            acc[3*h]   = fmaf(p, vr[3*h],   acc[3*h]);
            acc[3*h+1] = fmaf(p, vr[3*h+1], acc[3*h+1]);
            acc[3*h+2] = fmaf(p, vr[3*h+2], acc[3*h+2]);
        }
    }

    float o[D_];
    #pragma unroll
    for (int h = 0; h < H_; h++) {
        const float inv = 1.0f / l[h];
        o[3*h]   = acc[3*h]   * inv;
        o[3*h+1] = acc[3*h+1] * inv;
        o[3*h+2] = acc[3*h+2] * inv;
    }

    // ---- out projection ---------------------------------------------------
    float ac[D_];
    #pragma unroll
    for (int r = 0; r < D_; r++) {
        float a = sW[612 + r];
        #pragma unroll
        for (int c = 0; c < D_; c++) a = fmaf(sW[468 + r * D_ + c], o[c], a);
        ac[r] = a;
    }

    // ---- quantum attention layer (analytic) --------------------------------
    // z_w = cos(ac_w + theta_w);  out_w = prod_{0..w} z (w>=1), out_0 = prod_{1..11} z
    float z[D_];
    #pragma unroll
    for (int w = 0; w < D_; w++) z[w] = cosf(ac[w] + sW[624 + w]);
    float aq[D_];
    {
        float run = z[0];
        #pragma unroll
        for (int w = 1; w < D_; w++) { run *= z[w]; aq[w] = run; }
        float r2 = z[1];
        #pragma unroll
        for (int w = 2; w < D_; w++) r2 *= z[w];
        aq[0] = r2;
    }

    // ---- LayerNorm 1 -------------------------------------------------------
    float h1[D_], x1[D_];
    {
        float m = 0.f;
        #pragma unroll
        for (int w = 0; w < D_; w++) { h1[w] = xr[w] + aq[w]; m += h1[w]; }
        m *= (1.0f / D_);
        float v = 0.f;
        #pragma unroll
        for (int w = 0; w < D_; w++) { const float d = h1[w] - m; v = fmaf(d, d, v); }
        v *= (1.0f / D_);
        const float rstd = rsqrtf(v + 1e-5f);
        #pragma unroll
        for (int w = 0; w < D_; w++)
            x1[w] = (h1[w] - m) * rstd * sW[960 + w] + sW[972 + w];
    }

    // ---- quantum FFN: lin1 -> circuit -> lin2 -> relu ----------------------
    float zf[D_];
    #pragma unroll
    for (int r = 0; r < D_; r++) {
        float a = sW[780 + r];
        #pragma unroll
        for (int c = 0; c < D_; c++) a = fmaf(sW[636 + r * D_ + c], x1[c], a);
        zf[r] = cosf(sW[792 + r]) * cosf(a);   // <Z> of RY(th)RX(a)|0>
    }
    float fq[D_];
    {
        float run = zf[0];
        #pragma unroll
        for (int w = 1; w < D_; w++) { run *= zf[w]; fq[w] = run; }
        float r2 = zf[1];
        #pragma unroll
        for (int w = 2; w < D_; w++) r2 *= zf[w];
        fq[0] = r2;
    }
    float y[D_];
    #pragma unroll
    for (int r = 0; r < D_; r++) {
        float a = sW[948 + r];
        #pragma unroll
        for (int c = 0; c < D_; c++) a = fmaf(sW[804 + r * D_ + c], fq[c], a);
        y[r] = fmaxf(a, 0.f);
    }

    // ---- LayerNorm 2 + store -----------------------------------------------
    {
        float h2[D_];
        float m = 0.f;
        #pragma unroll
        for (int w = 0; w < D_; w++) { h2[w] = x1[w] + y[w]; m += h2[w]; }
        m *= (1.0f / D_);
        float v = 0.f;
        #pragma unroll
        for (int w = 0; w < D_; w++) { const float d = h2[w] - m; v = fmaf(d, d, v); }
        v *= (1.0f / D_);
        const float rstd = rsqrtf(v + 1e-5f);
        float res[D_];
        #pragma unroll
        for (int w = 0; w < D_; w++)
            res[w] = (h2[w] - m) * rstd * sW[984 + w] + sW[996 + w];
        float4* orow = (float4*)(out + (size_t)(b * T_ + tq) * D_);
        orow[0] = make_float4(res[0], res[1], res[2],  res[3]);
        orow[1] = make_float4(res[4], res[5], res[6],  res[7]);
        orow[2] = make_float4(res[8], res[9], res[10], res[11]);
    }
}

}  // namespace

extern "C" void kernel_launch(void* const* d_in, const int* in_sizes, int n_in,
                              void* d_out, int out_size) {
    (void)in_sizes; (void)n_in; (void)out_size;
    qtb_kernel<<<B_ * BPB, QPB>>>(
        (const float*)d_in[0],   // x
        (const float*)d_in[1],   // in_proj_w
        (const float*)d_in[2],   // in_proj_b
        (const float*)d_in[3],   // out_proj_w
        (const float*)d_in[4],   // out_proj_b
        (const float*)d_in[5],   // attn_theta
        (const float*)d_in[6],   // lin1_w
        (const float*)d_in[7],   // lin1_b
        (const float*)d_in[8],   // ffn_theta
        (const float*)d_in[9],   // lin2_w
        (const float*)d_in[10],  // lin2_b
        (const float*)d_in[11],  // ln1_g
        (const float*)d_in[12],  // ln1_b
        (const float*)d_in[13],  // ln2_g
        (const float*)d_in[14],  // ln2_b
        (const int*)d_in[15],    // mask
        (float*)d_out);
}